// round 13
// baseline (speedup 1.0000x reference)
#include <cuda_runtime.h>
#include <math.h>

// Shapes: B=2, S=8192 -> R=16384 rows; H=2048 (=512 float4); P=512; 3P=1536; 64 slots
#define GRID     148
#define TPB      1024
#define R_ROWS   16384
#define H_DIM    2048
#define H4       512
#define P_DIM    512
#define G_DIM    1536
#define N_SLOTS  64

// Phase-A row split: 104 blocks x 111 rows + 44 blocks x 110 rows = 16384.
#define NB_BIG   104
#define ROWS_A   111
#define ROWS_B   110

// Output layout (fp32, concatenated)
#define OFF_SURPRISE 0
#define OFF_ERR      1
#define OFF_PRED     2049
#define OFF_MEM      4097
#define OFF_STR      135169
#define OFF_PSTATE   135233

// Device scratch
__device__ __align__(16) float4 g_part[GRID * H4];   // per-block reduce partials
__device__ __align__(16) float  g_actual[H_DIM];
__device__ __align__(16) float  g_predicted[H_DIM];
__device__ __align__(16) float  g_xgru[H_DIM];
__device__ __align__(16) float  g_gi[G_DIM];
__device__ __align__(16) float  g_gh[G_DIM];
__device__ float    g_sumsq;
__device__ unsigned g_count   = 0;   // barrier arrivals (self-resetting)
__device__ unsigned g_release = 0;   // toggles 1,0,1,0 -> ends 0 (replay-safe)

__device__ __forceinline__ float warp_sum(float v) {
#pragma unroll
    for (int o = 16; o > 0; o >>= 1) v += __shfl_xor_sync(0xFFFFFFFFu, v, o);
    return v;
}
__device__ __forceinline__ float sigmoidf_(float x) { return 1.0f / (1.0f + expf(-x)); }

// Streaming sum of NR rows at stride 2*H4 float4s (parity-split).
// R4-proven shape: unroll-8, 2 accumulator chains, bounded register pressure.
template<int NR>
__device__ __forceinline__ float4 sum_stride2(const float4* __restrict__ p) {
    float4 a0 = make_float4(0.f,0.f,0.f,0.f), a1 = a0;
    constexpr int NE = NR & ~1;
#pragma unroll 8
    for (int j = 0; j < NE; j += 2) {
        float4 v0 = __ldcs(p + (size_t)(j    ) * (2 * H4));
        float4 v1 = __ldcs(p + (size_t)(j + 1) * (2 * H4));
        a0.x += v0.x; a0.y += v0.y; a0.z += v0.z; a0.w += v0.w;
        a1.x += v1.x; a1.y += v1.y; a1.z += v1.z; a1.w += v1.w;
    }
    if (NR & 1) {
        float4 v0 = __ldcs(p + (size_t)NE * (2 * H4));
        a0.x += v0.x; a0.y += v0.y; a0.z += v0.z; a0.w += v0.w;
    }
    float4 a; a.x = a0.x + a1.x; a.y = a0.y + a1.y; a.z = a0.z + a1.z; a.w = a0.w + a1.w;
    return a;
}

// Grid-wide barrier (toggle release 1,0,1,0). 148 blocks co-resident
// (1 block/SM via __launch_bounds__(1024,1)).
__device__ __forceinline__ void grid_bar(unsigned expect) {
    __syncthreads();
    if (threadIdx.x == 0) {
        __threadfence();
        unsigned t = atomicAdd(&g_count, 1u);
        if (t == GRID - 1) {
            atomicExch(&g_count, 0u);
            __threadfence();
            atomicExch(&g_release, expect);
        } else {
            while (*(volatile unsigned*)&g_release != expect) __nanosleep(64);
        }
        __threadfence();
    }
    __syncthreads();
}

__global__ void __launch_bounds__(TPB, 1)
k_fused(const float4* __restrict__ hs,       // hidden_states (16384 x 512 float4)
        const float*  __restrict__ pstate,   // (512,)
        const float4* __restrict__ mem4,     // mem_states (64 x 512 float4)
        const float*  __restrict__ strength, // (64,)
        const float*  __restrict__ Wih,      // (1536,2048)
        const float*  __restrict__ Whh,      // (1536,512)
        const float*  __restrict__ bih,
        const float*  __restrict__ bhh,
        const float*  __restrict__ ppw,      // (2048,512)
        const float*  __restrict__ ipw,      // (2048,2048)
        const float*  __restrict__ scale,
        const int*    __restrict__ wptr,
        float* __restrict__ out) {
    __shared__ float4 shv[H4];      // 8KB staging
    __shared__ float4 sfin[16];

    const int b = blockIdx.x, t = threadIdx.x;
    const int lane = t & 31, w = t >> 5;

    // ============ Phase A: uniform reduce on ALL blocks + predicted ==========
    {
        const int c = t & 511;            // float4 column
        const int par = t >> 9;           // 0/1 row parity
        int row0 = (b < NB_BIG) ? b * ROWS_A
                                : NB_BIG * ROWS_A + (b - NB_BIG) * ROWS_B;
        const float4* p = hs + (size_t)(row0 + par) * H4 + c;
        float4 a;
        if (b < NB_BIG) a = par ? sum_stride2<ROWS_A / 2>(p)          // 55
                                : sum_stride2<(ROWS_A + 1) / 2>(p);   // 56
        else            a = sum_stride2<ROWS_B / 2>(p);               // 55
        if (par) shv[c] = a;
        __syncthreads();
        if (!par) {
            float4 o = shv[c];
            a.x += o.x; a.y += o.y; a.z += o.z; a.w += o.w;
            g_part[b * H4 + c] = a;
        }
    }
    {
        // predicted = ppw @ pstate : 14 rows per block, warps 0..13
        int r = b * 14 + w;
        if (w < 14 && r < H_DIM) {
            const float4* s4 = reinterpret_cast<const float4*>(pstate);
            const float4* wr = reinterpret_cast<const float4*>(ppw + (size_t)r * P_DIM);
            float acc = 0.f;
#pragma unroll
            for (int j = 0; j < 4; j++) {
                float4 wv = wr[lane + 32 * j];
                float4 xv = __ldg(s4 + lane + 32 * j);
                acc += wv.x * xv.x + wv.y * xv.y + wv.z * xv.z + wv.w * xv.w;
            }
            acc = warp_sum(acc);
            if (lane == 0) { g_predicted[r] = acc; out[OFF_PRED + r] = acc; }
        }
        if (b == GRID - 1 && t == 0) g_sumsq = 0.f;
    }

    grid_bar(1);

    // ============ Phase B: finalize columns (148 partials) ==================
    if (b < 128) {
        int g = t >> 7;       // 0..7 (only 0..3 active)
        int p = t & 127;
        float4 s = make_float4(0.f,0.f,0.f,0.f);
        int col = b * 4 + g;
        if (g < 4) {
            s = g_part[p * H4 + col];
            if (p < GRID - 128) {
                float4 e = g_part[(128 + p) * H4 + col];
                s.x += e.x; s.y += e.y; s.z += e.z; s.w += e.w;
            }
        }
#pragma unroll
        for (int o = 16; o > 0; o >>= 1) {
            s.x += __shfl_xor_sync(0xFFFFFFFFu, s.x, o);
            s.y += __shfl_xor_sync(0xFFFFFFFFu, s.y, o);
            s.z += __shfl_xor_sync(0xFFFFFFFFu, s.z, o);
            s.w += __shfl_xor_sync(0xFFFFFFFFu, s.w, o);
        }
        if (g < 4 && lane == 0) sfin[g * 4 + ((t >> 5) & 3)] = s;
        __syncthreads();
        if (g < 4 && p == 0) {
            float4 a = make_float4(0.f,0.f,0.f,0.f);
#pragma unroll
            for (int i = 0; i < 4; i++) {
                float4 v = sfin[g * 4 + i];
                a.x += v.x; a.y += v.y; a.z += v.z; a.w += v.w;
            }
            const float inv = 1.0f / (float)R_ROWS;
            a.x *= inv; a.y *= inv; a.z *= inv; a.w *= inv;
            reinterpret_cast<float4*>(g_actual)[col] = a;
            float4 pd = reinterpret_cast<const float4*>(g_predicted)[col];
            float ex = a.x - pd.x, ey = a.y - pd.y, ez = a.z - pd.z, ew = a.w - pd.w;
            float* eo = out + OFF_ERR + col * 4;
            eo[0] = ex; eo[1] = ey; eo[2] = ez; eo[3] = ew;
            atomicAdd(&g_sumsq, ex * ex + ey * ey + ez * ez + ew * ew);
        }
    }

    grid_bar(0);

    // ============ Phase C: ipw rows + gh + mem/slot/strength/surprise =======
    if (t < H4) shv[t] = reinterpret_cast<const float4*>(g_actual)[t];
    __syncthreads();
    if (w < 14) {
        // x_gru rows, block-contiguous (as R9)
        int r = b * 14 + w;
        if (r < H_DIM) {
            const float4* wr = reinterpret_cast<const float4*>(ipw + (size_t)r * H_DIM);
            float acc = 0.f;
#pragma unroll
            for (int j = 0; j < 16; j++) {
                float4 wv = wr[lane + 32 * j];
                float4 xv = shv[lane + 32 * j];
                acc += wv.x * xv.x + wv.y * xv.y + wv.z * xv.z + wv.w * xv.w;
            }
            acc = warp_sum(acc);
            if (lane == 0) g_xgru[r] = acc;
        }
    } else if (w < 25) {
        // gh = Whh @ pstate + bhh : 11 rows per block, block-contiguous
        int r = b * 11 + (w - 14);
        if (r < G_DIM) {
            const float4* s4 = reinterpret_cast<const float4*>(pstate);
            const float4* wr = reinterpret_cast<const float4*>(Whh + (size_t)r * P_DIM);
            float acc = 0.f;
#pragma unroll
            for (int j = 0; j < 4; j++) {
                float4 wv = wr[lane + 32 * j];
                float4 xv = __ldg(s4 + lane + 32 * j);
                acc += wv.x * xv.x + wv.y * xv.y + wv.z * xv.z + wv.w * xv.w;
            }
            acc = warp_sum(acc);
            if (lane == 0) g_gh[r] = acc + bhh[r];
        }
    } else {
        // mem_states_new + strength + surprise. Unit m of 32 float4s.
        int m = b * 7 + (w - 25);            // 0..1035
        int slot = wptr[0] & (N_SLOTS - 1);
        if (m < 1024) {
            int idx = m * 32 + lane;         // float4 index 0..32767
            int row = m >> 4;                // 16 units per row
            float4 v;
            if (row == slot) {
                float sp = sigmoidf_(scale[0] * sqrtf(g_sumsq) * rsqrtf((float)H_DIM));
                float4 a = reinterpret_cast<const float4*>(g_actual)[idx & (H4 - 1)];
                v.x = a.x * sp; v.y = a.y * sp; v.z = a.z * sp; v.w = a.w * sp;
            } else {
                v = __ldg(mem4 + idx);
            }
            float* d = out + OFF_MEM + (size_t)idx * 4;   // OFF_MEM odd -> scalar
            d[0] = v.x; d[1] = v.y; d[2] = v.z; d[3] = v.w;
        } else if (m < 1026) {
            int i = (m - 1024) * 32 + lane;  // strength 0..63
            float sp = sigmoidf_(scale[0] * sqrtf(g_sumsq) * rsqrtf((float)H_DIM));
            float dec = (float)exp(8192.0 * log(0.999));
            out[OFF_STR + i] = (i == slot) ? sp : strength[i] * dec;
        } else if (m == 1026 && lane == 0) {
            out[OFF_SURPRISE] = sigmoidf_(scale[0] * sqrtf(g_sumsq) * rsqrtf((float)H_DIM));
        }
    }

    grid_bar(1);

    // ============ Phase D: gi = W_ih @ x_gru + b_ih =========================
    if (t < H4) shv[t] = reinterpret_cast<const float4*>(g_xgru)[t];
    __syncthreads();
    {
        int r = b * 11 + w;
        if (w < 11 && r < G_DIM) {
            const float4* wr = reinterpret_cast<const float4*>(Wih + (size_t)r * H_DIM);
            float acc = 0.f;
#pragma unroll
            for (int j = 0; j < 16; j++) {
                float4 wv = wr[lane + 32 * j];
                float4 xv = shv[lane + 32 * j];
                acc += wv.x * xv.x + wv.y * xv.y + wv.z * xv.z + wv.w * xv.w;
            }
            acc = warp_sum(acc);
            if (lane == 0) g_gi[r] = acc + bih[r];
        }
    }

    grid_bar(0);

    // ============ Phase E: GRU combine (block 0) ============================
    if (b == 0 && t < P_DIM) {
        float r = sigmoidf_(g_gi[t]             + g_gh[t]);
        float z = sigmoidf_(g_gi[P_DIM + t]     + g_gh[P_DIM + t]);
        float n = tanhf(g_gi[2 * P_DIM + t] + r * g_gh[2 * P_DIM + t]);
        out[OFF_PSTATE + t] = (1.0f - z) * n + z * pstate[t];
    }
}

extern "C" void kernel_launch(void* const* d_in, const int* in_sizes, int n_in,
                              void* d_out, int out_size) {
    const float* hidden     = (const float*)d_in[0];
    const float* pred_state = (const float*)d_in[1];
    const float* mem_states = (const float*)d_in[2];
    const float* mem_str    = (const float*)d_in[3];
    const float* W_ih       = (const float*)d_in[4];
    const float* W_hh       = (const float*)d_in[5];
    const float* b_ih       = (const float*)d_in[6];
    const float* b_hh       = (const float*)d_in[7];
    const float* pp_w       = (const float*)d_in[8];
    const float* ip_w       = (const float*)d_in[9];
    const float* s_scale    = (const float*)d_in[10];
    const int*   write_ptr  = (const int*)d_in[11];
    float* out = (float*)d_out;

    k_fused<<<GRID, TPB>>>((const float4*)hidden, pred_state,
                           (const float4*)mem_states, mem_str,
                           W_ih, W_hh, b_ih, b_hh, pp_w, ip_w,
                           s_scale, write_ptr, out);
}